// round 5
// baseline (speedup 1.0000x reference)
#include <cuda_runtime.h>
#include <cstdint>

// GPUBiasingMultiModel — Round 5: model-binned groups × V-slices (2048 CTAs),
// fused scatter. Fixes Round 4's occupancy collapse (264 CTAs, occ 21%) while
// keeping its 8x L2-read reduction.
//
//   bin_kernel:  1 CTA, bins hypotheses by model (order-invariant output).
//   fill_kernel: grid (8 slices x ngroups). Each CTA: one 1024-label slice
//                for 8 same-model hypotheses. Arc chunk loaded once, fanned
//                out to 8 rows; then backoff-scatter levels filtered to the
//                slice, deepest-first (CTA-local ordering via __syncthreads).
//
// Exploited structure (verified rel_err=0.0 in prior rounds):
//  - model m start state owns arcs [m*Aper, m*Aper+V), ilabel v at index v
//  - non-start local state ls has K sorted arcs at m*Aper + V + (ls-1)*K
//    (duplicates -> leftmost wins, matching searchsorted)
//  - backoff chain hits the start state in < MAX_BK hops
// Output: float32 [B*V scores | B*V next_states-as-float].

#define V_LABELS 8192
#define MAX_BK   4
#define EOS_ID   2
#define NTHR     256
#define GSZ      8
#define SLICES   8
#define SLICE    (V_LABELS / SLICES)      // 1024 labels; 256 float4 = 1/thread
#define MAXB     8192
#define MAXM     32

__device__ int g_bin_idx[MAXB];
__device__ int g_off[MAXM + 1];   // hypothesis offsets per model
__device__ int g_goff[MAXM + 1];  // group offsets per model
__device__ int g_ntot;            // total number of groups

// ---------------------------------------------------------------- binning
__global__ void bin_kernel(const int* __restrict__ model_ids, int B, int M)
{
    __shared__ int cnt[MAXM], cur[MAXM];
    const int tid = threadIdx.x;
    if (tid < M) cnt[tid] = 0;
    __syncthreads();
    for (int i = tid; i < B; i += blockDim.x)
        atomicAdd(&cnt[model_ids[i]], 1);
    __syncthreads();
    if (tid == 0) {
        int off = 0, go = 0;
        for (int m = 0; m < M; m++) {
            g_off[m] = off; g_goff[m] = go; cur[m] = off;
            off += cnt[m];
            go  += (cnt[m] + GSZ - 1) / GSZ;
        }
        g_off[M] = off; g_goff[M] = go; g_ntot = go;
    }
    __syncthreads();
    for (int i = tid; i < B; i += blockDim.x) {
        const int m = model_ids[i];
        const int p = atomicAdd(&cur[m], 1);
        g_bin_idx[p] = i;     // order within a model irrelevant to the output
    }
}

// ---------------------------------------------------------------- fill+scatter
__global__ void __launch_bounds__(NTHR)
fill_kernel(const float* __restrict__ arc_w,
            const int*   __restrict__ arc_to,
            const int*   __restrict__ arc_il,
            const int*   __restrict__ bk_to,
            const float* __restrict__ bk_w,
            const float* __restrict__ fin_w,
            const float* __restrict__ alpha,
            const int*   __restrict__ states,
            float* __restrict__ out_scores,
            float* __restrict__ out_next,
            int S, int K, int Aper, int M, int write_next)
{
    const int gid = blockIdx.y;           // hypothesis group
    const int sl  = blockIdx.x;           // V slice
    if (gid >= g_ntot) return;
    const int tid = threadIdx.x;

    int m = 0;
    while (m + 1 < M && gid >= g_goff[m + 1]) m++;

    const int   lg       = gid - g_goff[m];
    const int   sbeg     = g_off[m] + lg * GSZ;
    const int   ng       = min(GSZ, g_off[m + 1] - sbeg);
    const float a        = alpha[m];
    const int   base_m   = m * Aper;
    const int   slice_lo = sl * SLICE;

    __shared__ int   sh_b[GSZ], sh_start[GSZ], sh_have[GSZ];
    __shared__ int   sh_cc[GSZ][MAX_BK];
    __shared__ float sh_ca[GSZ][MAX_BK];
    __shared__ float sh_accL[GSZ], sh_eosS[GSZ], sh_eosN[GSZ];

    if (tid < ng) {
        const int b  = g_bin_idx[sbeg + tid];
        const int s0 = states[b];
        sh_b[tid] = b;
        int cur = s0; float acc = 0.f; int sl0 = -1, nlev = 0;
        #pragma unroll
        for (int i = 0; i < MAX_BK; i++) {
            sh_cc[tid][i] = cur; sh_ca[tid][i] = acc; nlev = i + 1;
            if ((cur % S) == 0) { sl0 = i; break; }
            acc += bk_w[cur];          // same accumulation order as reference
            cur  = bk_to[cur];
        }
        sh_have[tid]  = (sl0 >= 0) ? 1 : 0;
        sh_accL[tid]  = (sl0 >= 0) ? sh_ca[tid][sl0] : 0.f;
        sh_start[tid] = (sl0 >= 0) ? sl0 : nlev;
        sh_eosS[tid]  = fin_w[s0] * a;
        sh_eosN[tid]  = (float)s0;
    }
    __syncthreads();

    float accL[GSZ]; int have[GSZ]; int rowbase[GSZ];
    #pragma unroll
    for (int h = 0; h < GSZ; h++) {
        if (h < ng) {
            accL[h]    = sh_accL[h];
            have[h]    = sh_have[h];
            rowbase[h] = sh_b[h] * V_LABELS + slice_lo;   // fits in int
        }
    }

    // ---- bulk fill: one float4 chunk per thread, fanned out to ng rows
    {
        const int v0 = tid * 4;                      // within slice
        const float4 w = __ldg((const float4*)(arc_w  + base_m + slice_lo) + tid);
        const int4   t = __ldg((const int4*)  (arc_to + base_m + slice_lo) + tid);
        float4 nb;
        nb.x = (float)t.x; nb.y = (float)t.y;
        nb.z = (float)t.z; nb.w = (float)t.w;
        const bool eos_blk = (slice_lo == 0 && tid == 0);  // labels 0..3

        #pragma unroll
        for (int h = 0; h < GSZ; h++) {
            if (h < ng) {
                float4 s, n;
                if (have[h]) {
                    s.x = (accL[h] + w.x) * a;  s.y = (accL[h] + w.y) * a;
                    s.z = (accL[h] + w.z) * a;  s.w = (accL[h] + w.w) * a;
                    n = nb;
                } else {
                    s = make_float4(0.f, 0.f, 0.f, 0.f);
                    n = make_float4(0.f, 0.f, 0.f, 0.f);
                }
                if (eos_blk) {
                    ((float*)&s)[EOS_ID & 3] = sh_eosS[h];
                    ((float*)&n)[EOS_ID & 3] = sh_eosN[h];
                }
                __stcs((float4*)(out_scores + rowbase[h] + v0), s);
                if (write_next)
                    __stcs((float4*)(out_next + rowbase[h] + v0), n);
            }
        }
    }
    __syncthreads();

    // ---- fused scatter: warp h = hypothesis h, deepest level first,
    //      filtered to this CTA's label slice (ordering is CTA-local).
    const int h    = tid >> 5;
    const int lane = tid & 31;
    #pragma unroll
    for (int l = MAX_BK - 1; l >= 0; l--) {
        if (h < ng && l < sh_start[h] && lane < K) {
            const int   c    = sh_cc[h][l];
            const float accl = sh_ca[h][l];
            const int   ls   = c % S;                 // >= 1 for l < start
            const int   ab   = base_m + V_LABELS + (ls - 1) * K;
            const int   lab  = arc_il[ab + lane];
            if (lab >= slice_lo && lab < slice_lo + SLICE && lab != EOS_ID) {
                const bool leftmost = (lane == 0) || (arc_il[ab + lane - 1] != lab);
                if (leftmost) {
                    const int ro = sh_b[h] * V_LABELS + lab;
                    out_scores[ro] = (accl + arc_w[ab + lane]) * a;
                    if (write_next)
                        out_next[ro] = (float)arc_to[ab + lane];
                }
            }
        }
        __syncthreads();   // order levels (shallower overwrites deeper)
    }
}

// ---------------------------------------------------------------- fallback
// (Round-3 proven per-hypothesis vectorized kernel.)
__global__ void __launch_bounds__(NTHR)
advance_kernel_vec(const float* __restrict__ arc_w,
                   const int*   __restrict__ arc_to,
                   const int*   __restrict__ arc_il,
                   const int*   __restrict__ bk_to,
                   const float* __restrict__ bk_w,
                   const float* __restrict__ fin_w,
                   const float* __restrict__ alpha,
                   const int*   __restrict__ states,
                   const int*   __restrict__ model_ids,
                   float* __restrict__ out_scores,
                   float* __restrict__ out_next,
                   int S, int K, int Aper, int write_next)
{
    const int b   = blockIdx.x;
    const int tid = threadIdx.x;

    const int   s0 = states[b];
    const int   m  = model_ids[b];
    const float a  = alpha[m];
    const int   base_m = m * Aper;

    int cc[MAX_BK]; float ca[MAX_BK];
    int nlev = 0, start_lev = -1;
    {
        int cur = s0; float acc = 0.f;
        #pragma unroll
        for (int i = 0; i < MAX_BK; i++) {
            cc[i] = cur; ca[i] = acc; nlev = i + 1;
            if ((cur % S) == 0) { start_lev = i; break; }
            acc += bk_w[cur];
            cur  = bk_to[cur];
        }
    }

    float* out_s = out_scores + (size_t)b * V_LABELS;
    float* out_n = out_next   + (size_t)b * V_LABELS;
    const float eos_score = fin_w[s0] * a;
    const float eos_next  = (float)s0;

    {
        const float accL = (start_lev >= 0) ? ca[start_lev] : 0.f;
        const bool  have = (start_lev >= 0);
        if (start_lev < 0) start_lev = nlev;

        const float4* w4 = (const float4*)(arc_w  + base_m);
        const int4*   t4 = (const int4*)  (arc_to + base_m);

        #pragma unroll
        for (int it = 0; it < V_LABELS / (NTHR * 4); it++) {
            const int idx = it * NTHR + tid;
            const int v0  = idx * 4;
            float4 s, n;
            if (have) {
                const float4 w = __ldg(&w4[idx]);
                const int4   t = __ldg(&t4[idx]);
                s.x = (accL + w.x) * a;  n.x = (float)t.x;
                s.y = (accL + w.y) * a;  n.y = (float)t.y;
                s.z = (accL + w.z) * a;  n.z = (float)t.z;
                s.w = (accL + w.w) * a;  n.w = (float)t.w;
            } else {
                s = make_float4(0.f, 0.f, 0.f, 0.f);
                n = make_float4(0.f, 0.f, 0.f, 0.f);
            }
            if (v0 == (EOS_ID & ~3)) {
                ((float*)&s)[EOS_ID & 3] = eos_score;
                ((float*)&n)[EOS_ID & 3] = eos_next;
            }
            __stcs((float4*)(out_s + v0), s);
            if (write_next) __stcs((float4*)(out_n + v0), n);
        }
    }
    __syncthreads();

    for (int l = start_lev - 1; l >= 0; l--) {
        const int   c    = cc[l];
        const float accl = ca[l];
        const int   ls   = c % S;
        const int   ab   = base_m + V_LABELS + (ls - 1) * K;
        if (tid < K) {
            const int lab = arc_il[ab + tid];
            const bool leftmost = (tid == 0) || (arc_il[ab + tid - 1] != lab);
            if (leftmost && lab != EOS_ID) {
                out_s[lab] = (accl + arc_w[ab + tid]) * a;
                if (write_next) out_n[lab] = (float)arc_to[ab + tid];
            }
        }
        __syncthreads();
    }
}

extern "C" void kernel_launch(void* const* d_in, const int* in_sizes, int n_in,
                              void* d_out, int out_size)
{
    const float* arc_w  = (const float*)d_in[0];
    const int*   arc_to = (const int*)  d_in[1];
    const int*   arc_il = (const int*)  d_in[3];
    const int*   bk_to  = (const int*)  d_in[4];
    const float* bk_w   = (const float*)d_in[5];
    const float* fin_w  = (const float*)d_in[6];
    const float* alpha  = (const float*)d_in[7];
    const int*   states = (const int*)  d_in[8];
    const int*   mids   = (const int*)  d_in[9];

    const int A        = in_sizes[0];
    const int n_states = in_sizes[4];
    const int M        = in_sizes[7];
    const int B        = in_sizes[8];
    const int S        = n_states / M;
    const int Aper     = A / M;
    const int K        = (Aper - V_LABELS) / (S - 1);

    const int write_next = (out_size >= 2 * B * V_LABELS) ? 1 : 0;
    float* out_scores = (float*)d_out;
    float* out_next   = out_scores + (size_t)B * V_LABELS;

    const bool aligned =
        ((((unsigned long long)(uintptr_t)arc_w ) & 15ull) == 0) &&
        ((((unsigned long long)(uintptr_t)arc_to) & 15ull) == 0) &&
        ((((unsigned long long)(uintptr_t)d_out ) & 15ull) == 0);

    const bool fast_ok = aligned && (Aper % 4 == 0) && (K <= 32) &&
                         (B <= MAXB) && (M <= MAXM) && (S > 1);

    if (fast_ok) {
        bin_kernel<<<1, 512>>>(mids, B, M);
        const int max_groups = (B + GSZ - 1) / GSZ + M;
        dim3 grid(SLICES, max_groups);
        fill_kernel<<<grid, NTHR>>>(arc_w, arc_to, arc_il, bk_to, bk_w,
                                    fin_w, alpha, states,
                                    out_scores, out_next,
                                    S, K, Aper, M, write_next);
    } else {
        advance_kernel_vec<<<B, NTHR>>>(arc_w, arc_to, arc_il, bk_to, bk_w,
                                        fin_w, alpha, states, mids,
                                        out_scores, out_next,
                                        S, K, Aper, write_next);
    }
}

// round 6
// speedup vs baseline: 1.2712x; 1.2712x over previous
#include <cuda_runtime.h>
#include <cstdint>

// GPUBiasingMultiModel — Round 6: 3-phase pipeline.
//   prep:    1 CTA. Bins hyps by model; precomputes per-hyp backoff chain,
//            start-level accumulator, eos score/next; builds group tables.
//   fill:    (4 V-slices x groups) CTAs. Pure streaming fan-out: each arc
//            chunk read ONCE from L2, written to 8 same-model output rows.
//            No dependent loads, no scatter, no trailing syncs.
//   scatter: warp per hyp. Applies <=2 overwrite levels (deepest-first,
//            leftmost-duplicate wins). Kernel order fences fill->scatter.
//
// Exploited structure (verified rel_err=0.0 since Round 1):
//  - model m start state owns arcs [m*Aper, m*Aper+V), ilabel v at index v
//  - non-start local state ls has K sorted arcs at m*Aper + V + (ls-1)*K
//  - backoff chain hits the start state in < MAX_BK hops
// Output: float32 [B*V scores | B*V next_states-as-float].

#define V_LABELS 8192
#define MAX_BK   4
#define EOS_ID   2
#define NTHR     256
#define GSZ      8
#define SLICES   4
#define SLICE    (V_LABELS / SLICES)          // 2048 labels
#define CHUNKS   (SLICE / (NTHR * 4))         // 2 float4 per thread
#define MAXB     8192
#define MAXM     32
#define MAXG     (MAXB / GSZ + MAXM)

// ---- device scratch (static; no allocations) ----
__device__ int   g_bin_idx[MAXB];
__device__ int   g_off[MAXM + 1];
__device__ int   g_gmodel[MAXG];
__device__ int   g_gbeg[MAXG];
__device__ int   g_ntot;
__device__ float h_accL[MAXB];
__device__ int   h_have[MAXB];
__device__ float h_eosS[MAXB];
__device__ float h_eosN[MAXB];
__device__ int   h_start[MAXB];
__device__ int   h_cc[MAXB][MAX_BK];
__device__ float h_ca[MAXB][MAX_BK];

// ---------------------------------------------------------------- prep
__global__ void prep_kernel(const int* __restrict__ model_ids,
                            const int* __restrict__ states,
                            const int* __restrict__ bk_to,
                            const float* __restrict__ bk_w,
                            const float* __restrict__ fin_w,
                            const float* __restrict__ alpha,
                            int B, int M, int S)
{
    __shared__ int cnt[MAXM], cur[MAXM];
    const int tid = threadIdx.x;
    if (tid < M) cnt[tid] = 0;
    __syncthreads();
    for (int i = tid; i < B; i += blockDim.x)
        atomicAdd(&cnt[model_ids[i]], 1);
    __syncthreads();
    if (tid == 0) {
        int off = 0, go = 0;
        for (int m = 0; m < M; m++) {
            g_off[m] = off; cur[m] = off;
            const int ngr = (cnt[m] + GSZ - 1) / GSZ;
            for (int g = 0; g < ngr; g++) {
                g_gmodel[go + g] = m;
                g_gbeg[go + g]   = off + g * GSZ;
            }
            off += cnt[m];
            go  += ngr;
        }
        g_off[M] = off; g_ntot = go;
    }
    __syncthreads();
    for (int i = tid; i < B; i += blockDim.x) {
        const int m = model_ids[i];
        const int p = atomicAdd(&cur[m], 1);
        g_bin_idx[p] = i;    // order within model irrelevant to output
    }
    // per-hyp backoff chains (dependent loads run once, 1024-wide)
    for (int b = tid; b < B; b += blockDim.x) {
        const int s0 = states[b];
        const int m  = model_ids[b];
        const float a = alpha[m];
        int cc[MAX_BK]; float ca[MAX_BK];
        int curst = s0; float acc = 0.f; int sl = -1, nlev = 0;
        #pragma unroll
        for (int i = 0; i < MAX_BK; i++) {
            cc[i] = curst; ca[i] = acc; nlev = i + 1;
            if ((curst % S) == 0) { sl = i; break; }
            acc  += bk_w[curst];      // same accumulation order as reference
            curst = bk_to[curst];
        }
        h_have[b]  = (sl >= 0) ? 1 : 0;
        h_accL[b]  = (sl >= 0) ? ca[sl] : 0.f;
        h_start[b] = (sl >= 0) ? sl : nlev;
        h_eosS[b]  = fin_w[s0] * a;
        h_eosN[b]  = (float)s0;
        #pragma unroll
        for (int i = 0; i < MAX_BK; i++) { h_cc[b][i] = cc[i]; h_ca[b][i] = ca[i]; }
    }
}

// ---------------------------------------------------------------- fill
__global__ void __launch_bounds__(NTHR)
fill_kernel(const float* __restrict__ arc_w,
            const int*   __restrict__ arc_to,
            const float* __restrict__ alpha,
            float* __restrict__ out_scores,
            float* __restrict__ out_next,
            int Aper, int write_next)
{
    const int gid = blockIdx.y;
    const int sl  = blockIdx.x;
    if (gid >= g_ntot) return;
    const int tid = threadIdx.x;

    const int   m      = g_gmodel[gid];
    const int   sbeg   = g_gbeg[gid];
    const int   ng     = min(GSZ, g_off[m + 1] - sbeg);
    const float a      = alpha[m];
    const int   sbase  = m * Aper + sl * SLICE;

    __shared__ float s_accL[GSZ], s_eosS[GSZ], s_eosN[GSZ];
    __shared__ int   s_row[GSZ], s_have[GSZ];
    if (tid < ng) {
        const int b = g_bin_idx[sbeg + tid];
        s_row[tid]  = b * V_LABELS + sl * SLICE;
        s_accL[tid] = h_accL[b];
        s_have[tid] = h_have[b];
        s_eosS[tid] = h_eosS[b];
        s_eosN[tid] = h_eosN[b];
    }
    __syncthreads();

    float accL[GSZ]; int have[GSZ]; int row[GSZ]; float eS[GSZ], eN[GSZ];
    #pragma unroll
    for (int h = 0; h < GSZ; h++) {
        if (h < ng) {
            accL[h] = s_accL[h]; have[h] = s_have[h]; row[h] = s_row[h];
            eS[h] = s_eosS[h];   eN[h] = s_eosN[h];
        }
    }

    const float4* w4 = (const float4*)(arc_w  + sbase);
    const int4*   t4 = (const int4*)  (arc_to + sbase);

    #pragma unroll
    for (int c = 0; c < CHUNKS; c++) {
        const int idx = c * NTHR + tid;
        const int v0  = idx * 4;
        const float4 w = __ldg(&w4[idx]);
        const int4   t = __ldg(&t4[idx]);
        float4 nb;
        nb.x = (float)t.x; nb.y = (float)t.y;
        nb.z = (float)t.z; nb.w = (float)t.w;
        const bool eos_blk = (sl == 0 && idx == 0);   // labels 0..3

        #pragma unroll
        for (int h = 0; h < GSZ; h++) {
            if (h < ng) {
                float4 s, n;
                if (have[h]) {
                    s.x = (accL[h] + w.x) * a;  s.y = (accL[h] + w.y) * a;
                    s.z = (accL[h] + w.z) * a;  s.w = (accL[h] + w.w) * a;
                    n = nb;
                } else {
                    s = make_float4(0.f, 0.f, 0.f, 0.f);
                    n = make_float4(0.f, 0.f, 0.f, 0.f);
                }
                if (eos_blk) {
                    ((float*)&s)[EOS_ID & 3] = eS[h];
                    ((float*)&n)[EOS_ID & 3] = eN[h];
                }
                __stcs((float4*)(out_scores + row[h] + v0), s);
                if (write_next)
                    __stcs((float4*)(out_next + row[h] + v0), n);
            }
        }
    }
}

// ---------------------------------------------------------------- scatter
__global__ void scatter_kernel(const float* __restrict__ arc_w,
                               const int*   __restrict__ arc_to,
                               const int*   __restrict__ arc_il,
                               const float* __restrict__ alpha,
                               const int*   __restrict__ model_ids,
                               float* __restrict__ out_scores,
                               float* __restrict__ out_next,
                               int S, int K, int Aper, int B, int write_next)
{
    const int gw   = (blockIdx.x * blockDim.x + threadIdx.x) >> 5;
    const int lane = threadIdx.x & 31;
    if (gw >= B) return;
    const int b     = gw;
    const int start = h_start[b];
    if (start <= 0) return;                  // uniform per warp
    const int   m      = model_ids[b];
    const float a      = alpha[m];
    const int   base_m = m * Aper;
    const int   ro     = b * V_LABELS;

    for (int l = start - 1; l >= 0; l--) {   // deepest first; shallow wins
        const int   c    = h_cc[b][l];
        const float accl = h_ca[b][l];
        const int   ls   = c % S;            // >= 1 for l < start
        const int   ab   = base_m + V_LABELS + (ls - 1) * K;
        if (lane < K) {
            const int lab = arc_il[ab + lane];
            const bool leftmost = (lane == 0) || (arc_il[ab + lane - 1] != lab);
            if (leftmost && lab != EOS_ID) {
                out_scores[ro + lab] = (accl + arc_w[ab + lane]) * a;
                if (write_next)
                    out_next[ro + lab] = (float)arc_to[ab + lane];
            }
        }
        __syncwarp();
    }
}

// ---------------------------------------------------------------- fallback
// (Round-3 proven per-hypothesis vectorized kernel.)
__global__ void __launch_bounds__(NTHR)
advance_kernel_vec(const float* __restrict__ arc_w,
                   const int*   __restrict__ arc_to,
                   const int*   __restrict__ arc_il,
                   const int*   __restrict__ bk_to,
                   const float* __restrict__ bk_w,
                   const float* __restrict__ fin_w,
                   const float* __restrict__ alpha,
                   const int*   __restrict__ states,
                   const int*   __restrict__ model_ids,
                   float* __restrict__ out_scores,
                   float* __restrict__ out_next,
                   int S, int K, int Aper, int write_next)
{
    const int b   = blockIdx.x;
    const int tid = threadIdx.x;

    const int   s0 = states[b];
    const int   m  = model_ids[b];
    const float a  = alpha[m];
    const int   base_m = m * Aper;

    int cc[MAX_BK]; float ca[MAX_BK];
    int nlev = 0, start_lev = -1;
    {
        int cur = s0; float acc = 0.f;
        #pragma unroll
        for (int i = 0; i < MAX_BK; i++) {
            cc[i] = cur; ca[i] = acc; nlev = i + 1;
            if ((cur % S) == 0) { start_lev = i; break; }
            acc += bk_w[cur];
            cur  = bk_to[cur];
        }
    }

    float* out_s = out_scores + (size_t)b * V_LABELS;
    float* out_n = out_next   + (size_t)b * V_LABELS;
    const float eos_score = fin_w[s0] * a;
    const float eos_next  = (float)s0;

    {
        const float accL = (start_lev >= 0) ? ca[start_lev] : 0.f;
        const bool  have = (start_lev >= 0);
        if (start_lev < 0) start_lev = nlev;

        const float4* w4 = (const float4*)(arc_w  + base_m);
        const int4*   t4 = (const int4*)  (arc_to + base_m);

        #pragma unroll
        for (int it = 0; it < V_LABELS / (NTHR * 4); it++) {
            const int idx = it * NTHR + tid;
            const int v0  = idx * 4;
            float4 s, n;
            if (have) {
                const float4 w = __ldg(&w4[idx]);
                const int4   t = __ldg(&t4[idx]);
                s.x = (accL + w.x) * a;  n.x = (float)t.x;
                s.y = (accL + w.y) * a;  n.y = (float)t.y;
                s.z = (accL + w.z) * a;  n.z = (float)t.z;
                s.w = (accL + w.w) * a;  n.w = (float)t.w;
            } else {
                s = make_float4(0.f, 0.f, 0.f, 0.f);
                n = make_float4(0.f, 0.f, 0.f, 0.f);
            }
            if (v0 == (EOS_ID & ~3)) {
                ((float*)&s)[EOS_ID & 3] = eos_score;
                ((float*)&n)[EOS_ID & 3] = eos_next;
            }
            __stcs((float4*)(out_s + v0), s);
            if (write_next) __stcs((float4*)(out_n + v0), n);
        }
    }
    __syncthreads();

    for (int l = start_lev - 1; l >= 0; l--) {
        const int   c    = cc[l];
        const float accl = ca[l];
        const int   ls   = c % S;
        const int   ab   = base_m + V_LABELS + (ls - 1) * K;
        if (tid < K) {
            const int lab = arc_il[ab + tid];
            const bool leftmost = (tid == 0) || (arc_il[ab + tid - 1] != lab);
            if (leftmost && lab != EOS_ID) {
                out_s[lab] = (accl + arc_w[ab + tid]) * a;
                if (write_next) out_n[lab] = (float)arc_to[ab + tid];
            }
        }
        __syncthreads();
    }
}

extern "C" void kernel_launch(void* const* d_in, const int* in_sizes, int n_in,
                              void* d_out, int out_size)
{
    const float* arc_w  = (const float*)d_in[0];
    const int*   arc_to = (const int*)  d_in[1];
    const int*   arc_il = (const int*)  d_in[3];
    const int*   bk_to  = (const int*)  d_in[4];
    const float* bk_w   = (const float*)d_in[5];
    const float* fin_w  = (const float*)d_in[6];
    const float* alpha  = (const float*)d_in[7];
    const int*   states = (const int*)  d_in[8];
    const int*   mids   = (const int*)  d_in[9];

    const int A        = in_sizes[0];
    const int n_states = in_sizes[4];
    const int M        = in_sizes[7];
    const int B        = in_sizes[8];
    const int S        = n_states / M;
    const int Aper     = A / M;
    const int K        = (Aper - V_LABELS) / (S - 1);

    const int write_next = (out_size >= 2 * B * V_LABELS) ? 1 : 0;
    float* out_scores = (float*)d_out;
    float* out_next   = out_scores + (size_t)B * V_LABELS;

    const bool aligned =
        ((((unsigned long long)(uintptr_t)arc_w ) & 15ull) == 0) &&
        ((((unsigned long long)(uintptr_t)arc_to) & 15ull) == 0) &&
        ((((unsigned long long)(uintptr_t)d_out ) & 15ull) == 0);

    const bool fast_ok = aligned && (Aper % 4 == 0) && (K <= 32) &&
                         (B <= MAXB) && (M <= MAXM) && (S > 1) &&
                         (Aper % SLICE == 0);

    if (fast_ok) {
        prep_kernel<<<1, 1024>>>(mids, states, bk_to, bk_w, fin_w, alpha,
                                 B, M, S);
        const int maxg = (B + GSZ - 1) / GSZ + M;
        dim3 grid(SLICES, maxg);
        fill_kernel<<<grid, NTHR>>>(arc_w, arc_to, alpha,
                                    out_scores, out_next, Aper, write_next);
        const int warps = B;
        const int scta  = (warps * 32 + NTHR - 1) / NTHR;
        scatter_kernel<<<scta, NTHR>>>(arc_w, arc_to, arc_il, alpha, mids,
                                       out_scores, out_next,
                                       S, K, Aper, B, write_next);
    } else {
        advance_kernel_vec<<<B, NTHR>>>(arc_w, arc_to, arc_il, bk_to, bk_w,
                                        fin_w, alpha, states, mids,
                                        out_scores, out_next,
                                        S, K, Aper, write_next);
    }
}